// round 8
// baseline (speedup 1.0000x reference)
#include <cuda_runtime.h>
#include <cuda_bf16.h>
#include <cstdint>

#define BATCH 8
#define CC    64
#define DD    8
#define NPIX  4096

// 0.125 * log2(e), folded into K at proj time
#define KSCALE 0.18033688011112042f

// ---------------- device scratch ----------------
__device__ float         g_Q[BATCH * NPIX * DD];   // [b][n][d] fp32
__device__ float         g_K[BATCH * NPIX * DD];   // [b][m][d] fp32, pre-scaled
__device__ __nv_bfloat16 g_Vbf[BATCH * CC * NPIX]; // [b][c][m] bf16
__device__ float         g_Zp[4 * BATCH * NPIX];   // [split][b][m]
__device__ float         g_Rz[BATCH * NPIX];       // [b][m] 1/Z
__device__ float         g_y[BATCH * CC];          // [b][c]
__device__ float         g_O0[BATCH * CC];         // [b][c] term-1 output

__device__ __forceinline__ uint32_t f2tf32(float f) {
    uint32_t u; asm("cvt.rna.tf32.f32 %0, %1;" : "=r"(u) : "f"(f)); return u;
}
__device__ __forceinline__ float ex2(float x) {
    float r; asm("ex2.approx.f32 %0, %1;" : "=f"(r) : "f"(x)); return r;
}
__device__ __forceinline__ uint32_t bf2(float lo, float hi) {
    uint32_t r; asm("cvt.rn.bf16x2.f32 %0, %1, %2;" : "=r"(r) : "f"(hi), "f"(lo));
    return r;
}
__device__ __forceinline__ uint4 cvt4(float4 t) {
    uint4 u;
    u.x = f2tf32(t.x); u.y = f2tf32(t.y); u.z = f2tf32(t.z); u.w = f2tf32(t.w);
    return u;
}
__device__ __forceinline__ void mma_tf32(float* c, const uint32_t* a,
                                         uint32_t b0, uint32_t b1) {
    asm volatile(
        "mma.sync.aligned.m16n8k8.row.col.f32.tf32.tf32.f32 "
        "{%0,%1,%2,%3}, {%4,%5,%6,%7}, {%8,%9}, {%0,%1,%2,%3};"
        : "+f"(c[0]), "+f"(c[1]), "+f"(c[2]), "+f"(c[3])
        : "r"(a[0]), "r"(a[1]), "r"(a[2]), "r"(a[3]), "r"(b0), "r"(b1));
}
__device__ __forceinline__ void mma_bf16(float* c, const uint32_t* a,
                                         uint32_t b0, uint32_t b1) {
    asm volatile(
        "mma.sync.aligned.m16n8k16.row.col.f32.bf16.bf16.f32 "
        "{%0,%1,%2,%3}, {%4,%5,%6,%7}, {%8,%9}, {%0,%1,%2,%3};"
        : "+f"(c[0]), "+f"(c[1]), "+f"(c[2]), "+f"(c[3])
        : "r"(a[0]), "r"(a[1]), "r"(a[2]), "r"(a[3]), "r"(b0), "r"(b1));
}
__device__ __forceinline__ void cp_async16(uint32_t dst, const void* src) {
    asm volatile("cp.async.ca.shared.global [%0], [%1], 16;"
                 :: "r"(dst), "l"(src));
}

// ---------------- 1: projections, unified 80-channel weights ----------------
__global__ void __launch_bounds__(256) proj_kernel(
    const float* __restrict__ x,
    const float* __restrict__ Wq, const float* __restrict__ bq,
    const float* __restrict__ Wk, const float* __restrict__ bk,
    const float* __restrict__ Wv, const float* __restrict__ bv)
{
    __shared__ float sW[CC * 80];
    __shared__ float sB[80];
    const int tid = threadIdx.x;
    const int b = blockIdx.y;
    const int s = tid & 63;
    const int h = tid >> 6;
    const int ch0 = h * 20;

    for (int i = tid; i < CC * 80; i += 256) {
        int c = i / 80, j = i % 80;
        float w;
        if (j < 8)       w = Wq[j * CC + c];
        else if (j < 16) w = Wk[(j - 8) * CC + c] * KSCALE;
        else             w = Wv[(j - 16) * CC + c];
        sW[c * 80 + j] = w;
    }
    if (tid < 80) {
        float bb;
        if (tid < 8)       bb = bq[tid];
        else if (tid < 16) bb = bk[tid - 8] * KSCALE;
        else               bb = bv[tid - 16];
        sB[tid] = bb;
    }
    __syncthreads();

    float a[4][20];
#pragma unroll
    for (int p = 0; p < 4; p++)
#pragma unroll
        for (int j = 0; j < 20; j++) a[p][j] = 0.f;

    const int nb = blockIdx.x * 256 + s;
    const float* xb = x + ((size_t)b * CC << 12) + nb;
#pragma unroll 1
    for (int c = 0; c < CC; c += 2) {
        float x0[4], x1[4];
#pragma unroll
        for (int p = 0; p < 4; p++) {
            x0[p] = xb[((size_t)c << 12) + p * 64];
            x1[p] = xb[((size_t)(c + 1) << 12) + p * 64];
        }
        const float* w0 = sW + c * 80 + ch0;
        const float* w1 = sW + (c + 1) * 80 + ch0;
#pragma unroll
        for (int j = 0; j < 20; j++) {
            float ww0 = w0[j], ww1 = w1[j];
#pragma unroll
            for (int p = 0; p < 4; p++) {
                a[p][j] = fmaf(ww0, x0[p], a[p][j]);
                a[p][j] = fmaf(ww1, x1[p], a[p][j]);
            }
        }
    }

#pragma unroll
    for (int p = 0; p < 4; p++) {
        const int n = nb + p * 64;
        if (h == 0) {
            float4 q0 = make_float4(a[p][0] + sB[0], a[p][1] + sB[1],
                                    a[p][2] + sB[2], a[p][3] + sB[3]);
            float4 q1 = make_float4(a[p][4] + sB[4], a[p][5] + sB[5],
                                    a[p][6] + sB[6], a[p][7] + sB[7]);
            float4 k0 = make_float4(a[p][8] + sB[8], a[p][9] + sB[9],
                                    a[p][10] + sB[10], a[p][11] + sB[11]);
            float4 k1 = make_float4(a[p][12] + sB[12], a[p][13] + sB[13],
                                    a[p][14] + sB[14], a[p][15] + sB[15]);
            float4* qo = (float4*)(g_Q + ((b << 12) + n) * DD);
            qo[0] = q0; qo[1] = q1;
            float4* ko = (float4*)(g_K + ((b << 12) + n) * DD);
            ko[0] = k0; ko[1] = k1;
#pragma unroll
            for (int j = 16; j < 20; j++)
                g_Vbf[(((size_t)b * CC + (j - 16)) << 12) + n] =
                    __float2bfloat16(a[p][j] + sB[j]);
        } else {
#pragma unroll
            for (int j = 0; j < 20; j++) {
                int ch = ch0 - 16 + j;
                g_Vbf[(((size_t)b * CC + ch) << 12) + n] =
                    __float2bfloat16(a[p][j] + sB[ch0 + j]);
            }
        }
    }
}

// ---------------- 2: Z[m] = sum_n exp2(QK) via mma ----------------
__global__ void __launch_bounds__(256) zr_kernel()
{
    __shared__ uint32_t sK[64 * 12];
    __shared__ uint32_t sQ[128 * 12];
    __shared__ float    szp[8 * 64];

    const int tid  = threadIdx.x;
    const int lane = tid & 31;
    const int wid  = tid >> 5;
    const int g  = lane >> 2;
    const int tg = lane & 3;
    const int b = blockIdx.z;
    const int ns = blockIdx.y;
    const int m_base = blockIdx.x * 64;

    if (tid < 128) {
        float4 t = ((const float4*)(g_K + ((b << 12) + m_base) * DD))[tid];
        *(uint4*)(sK + (tid >> 1) * 12 + (tid & 1) * 4) = cvt4(t);
    }

    float zacc[16];
#pragma unroll
    for (int i = 0; i < 16; i++) zacc[i] = 0.f;

    for (int t = 0; t < 8; t++) {
        __syncthreads();
        {
            const int nb = ns * 1024 + t * 128;
            float4 tq = ((const float4*)(g_Q + ((b << 12) + nb) * DD))[tid];
            *(uint4*)(sQ + (tid >> 1) * 12 + (tid & 1) * 4) = cvt4(tq);
        }
        __syncthreads();

        const int nrow = wid * 16 + g;
        uint32_t a[4];
        a[0] = sQ[nrow * 12 + tg];
        a[1] = sQ[(nrow + 8) * 12 + tg];
        a[2] = sQ[nrow * 12 + tg + 4];
        a[3] = sQ[(nrow + 8) * 12 + tg + 4];

#pragma unroll
        for (int mt8 = 0; mt8 < 8; mt8++) {
            uint32_t b0 = sK[(mt8 * 8 + g) * 12 + tg];
            uint32_t b1 = sK[(mt8 * 8 + g) * 12 + tg + 4];
            float c[4] = {0.f, 0.f, 0.f, 0.f};
            mma_tf32(c, a, b0, b1);
            zacc[mt8 * 2 + 0] += ex2(c[0]) + ex2(c[2]);
            zacc[mt8 * 2 + 1] += ex2(c[1]) + ex2(c[3]);
        }
    }

#pragma unroll
    for (int i = 0; i < 16; i++) {
        zacc[i] += __shfl_xor_sync(0xffffffffu, zacc[i], 4);
        zacc[i] += __shfl_xor_sync(0xffffffffu, zacc[i], 8);
        zacc[i] += __shfl_xor_sync(0xffffffffu, zacc[i], 16);
    }
    if (lane < 4) {
#pragma unroll
        for (int i = 0; i < 16; i++)
            szp[wid * 64 + (i >> 1) * 8 + lane * 2 + (i & 1)] = zacc[i];
    }
    __syncthreads();
    if (tid < 64) {
        float z = 0.f;
#pragma unroll
        for (int w = 0; w < 8; w++) z += szp[w * 64 + tid];
        g_Zp[(ns * BATCH + b) * NPIX + m_base + tid] = z;
    }
}

// ---------------- 2b: Rz = 1/sum(Zp) ----------------
__global__ void __launch_bounds__(256) rza_kernel()
{
    int i = blockIdx.x * 256 + threadIdx.x;
    int b = i >> 12, m = i & 4095;
    float z = g_Zp[(0 * BATCH + b) * NPIX + m]
            + g_Zp[(1 * BATCH + b) * NPIX + m]
            + g_Zp[(2 * BATCH + b) * NPIX + m]
            + g_Zp[(3 * BATCH + b) * NPIX + m];
    g_Rz[i] = 1.0f / z;
}

// ---------------- 2c: y[b][c] = sum_m x[b][c][m] * rz[b][m] ----------------
__global__ void __launch_bounds__(256) o0a_kernel(const float* __restrict__ x)
{
    __shared__ float red[256];
    const int c = blockIdx.x, b = blockIdx.y, tid = threadIdx.x;
    const float4* xp = (const float4*)(x + (((size_t)b * CC + c) << 12));
    const float4* rz = (const float4*)(g_Rz + (b << 12));
    float acc = 0.f;
#pragma unroll
    for (int it = 0; it < 4; it++) {
        int m = it * 256 + tid;
        float4 xv = xp[m], rv = rz[m];
        acc = fmaf(xv.x, rv.x, acc);
        acc = fmaf(xv.y, rv.y, acc);
        acc = fmaf(xv.z, rv.z, acc);
        acc = fmaf(xv.w, rv.w, acc);
    }
    red[tid] = acc;
    __syncthreads();
    for (int s = 128; s; s >>= 1) {
        if (tid < s) red[tid] += red[tid + s];
        __syncthreads();
    }
    if (tid == 0) g_y[b * CC + c] = red[0];
}

// ---------------- 2d: O0[b][d] = Wv.y + bv*sum(rz) ----------------
__global__ void __launch_bounds__(64) o0b_kernel(
    const float* __restrict__ Wv, const float* __restrict__ bv)
{
    __shared__ float sred[64];
    __shared__ float sy[64];
    const int b = blockIdx.x, tid = threadIdx.x;
    const float* rz = g_Rz + (b << 12);
    float s = 0.f;
    for (int m = tid; m < NPIX; m += 64) s += rz[m];
    sred[tid] = s;
    sy[tid] = g_y[b * CC + tid];
    __syncthreads();
    for (int k = 32; k; k >>= 1) {
        if (tid < k) sred[tid] += sred[tid + k];
        __syncthreads();
    }
    float S = sred[0];
    float acc = bv[tid] * S;
    for (int c = 0; c < CC; c++)
        acc = fmaf(Wv[tid * CC + c], sy[c], acc);
    g_O0[b * CC + tid] = acc;
}

// ---------------- 3: term2, single-barrier pipelined ----------------
// smem u32 layout:
//   sPbf[2][128*36]  : 0     .. 9216
//   sVb [3][64*36]   : 9216  .. 16128
//   sQ  [128*12]     : 16128 .. 17664
//   sK  [2][64*12]   : 17664 .. 19200
//   sRz [2][64]      : 19200 .. 19328
#define OFF_PBF 0
#define PBF_SZ  4608
#define OFF_VB  9216
#define VB_SZ   2304
#define OFF_Q   16128
#define OFF_K   17664
#define K_SZ    768
#define OFF_RZ  19200
#define OUT_SMEM (19328 * 4)    // 77312 B

__global__ void __launch_bounds__(256, 2) out_kernel(float* __restrict__ out)
{
    extern __shared__ uint32_t sm[];
    const int tid  = threadIdx.x;
    const int lane = tid & 31;
    const int wid  = tid >> 5;
    const int b    = blockIdx.y;
    const int n_base = blockIdx.x * 128;
    const int g  = lane >> 2;
    const int tg = lane & 3;

    const int ws    = wid * 16;         // phase-A n rows
    const int Mwoff = (wid & 3) * 32;   // phase-B n offset
    const int mh    = wid >> 2;         // phase-B m-half

    // ---- prologue ----
    {   // Q tile
        const float4* qg = (const float4*)(g_Q + ((b << 12) + n_base) * DD);
        float4 t = qg[tid];
        *(uint4*)(sm + OFF_Q + (tid >> 1) * 12 + (tid & 1) * 4) = cvt4(t);
    }
    float4 vK = make_float4(0.f, 0.f, 0.f, 0.f);
    float vRz = 0.f;
    if (tid < 128) vK = ((const float4*)(g_K + (b << 12) * DD))[tid];
    if (tid < 64)  vRz = g_Rz[(b << 12) + tid];
    // store K(0)/rz(0) into buffer 0
    if (tid < 128)
        *(uint4*)(sm + OFF_K + (tid >> 1) * 12 + (tid & 1) * 4) = cvt4(vK);
    if (tid < 64) ((float*)(sm + OFF_RZ))[tid] = vRz;
    // prefetch K(1)/rz(1)
    if (tid < 128) vK = ((const float4*)(g_K + ((b << 12) + 64) * DD))[tid];
    if (tid < 64)  vRz = g_Rz[(b << 12) + 64 + tid];
    {   // cp.async V(0) -> vb[0]
        const char* src = (const char*)(g_Vbf + ((size_t)b * CC << 12));
#pragma unroll
        for (int k = 0; k < 2; k++) {
            int q = tid + k * 256;
            int row = q >> 3, off = (q & 7) * 16;
            uint32_t dst = (uint32_t)__cvta_generic_to_shared(
                (char*)(sm + OFF_VB) + row * 144 + off);
            cp_async16(dst, src + ((size_t)row << 13) + off);
        }
        asm volatile("cp.async.commit_group;");
    }
    __syncthreads();    // sQ, sK[0], sRz[0] visible

    uint32_t aq[4];
    aq[0] = sm[OFF_Q + (ws + g) * 12 + tg];
    aq[1] = sm[OFF_Q + (ws + g + 8) * 12 + tg];
    aq[2] = sm[OFF_Q + (ws + g) * 12 + tg + 4];
    aq[3] = sm[OFF_Q + (ws + g + 8) * 12 + tg + 4];

    float acc[64];
#pragma unroll
    for (int i = 0; i < 64; i++) acc[i] = 0.f;

    // ---- main loop: ONE barrier per tile ----
    for (int mt = 0; mt < 64; mt++) {
        const int par = mt & 1;
        uint32_t* sPb  = sm + OFF_PBF + par * PBF_SZ;
        const uint32_t* sKb = sm + OFF_K + par * K_SZ;
        const float* sRzb = (const float*)(sm + OFF_RZ + par * 64);

        // phase A(t): QK mma -> delta' -> bf16 into sPb
#pragma unroll
        for (int mt8 = 0; mt8 < 8; mt8++) {
            uint32_t b0 = sKb[(mt8 * 8 + g) * 12 + tg];
            uint32_t b1 = sKb[(mt8 * 8 + g) * 12 + tg + 4];
            float c[4] = {0.f, 0.f, 0.f, 0.f};
            mma_tf32(c, aq, b0, b1);
            float2 rr = *(const float2*)(sRzb + mt8 * 8 + tg * 2);
            float d0 = fmaf(ex2(c[0]), rr.x, -rr.x);
            float d1 = fmaf(ex2(c[1]), rr.y, -rr.y);
            float d2 = fmaf(ex2(c[2]), rr.x, -rr.x);
            float d3 = fmaf(ex2(c[3]), rr.y, -rr.y);
            sPb[(ws + g) * 36 + mt8 * 4 + tg]     = bf2(d0, d1);
            sPb[(ws + g + 8) * 36 + mt8 * 4 + tg] = bf2(d2, d3);
        }

        // store prefetched K(t+1)/rz(t+1) into other buffer
        if (mt < 63) {
            if (tid < 128)
                *(uint4*)(sm + OFF_K + (1 - par) * K_SZ
                          + (tid >> 1) * 12 + (tid & 1) * 4) = cvt4(vK);
            if (tid < 64) ((float*)(sm + OFF_RZ + (1 - par) * 64))[tid] = vRz;
        }
        // reg-prefetch K(t+2)/rz(t+2)
        if (mt < 62) {
            const int mb2 = (mt + 2) * 64;
            if (tid < 128)
                vK = ((const float4*)(g_K + ((b << 12) + mb2) * DD))[tid];
            if (tid < 64) vRz = g_Rz[(b << 12) + mb2 + tid];
        }
        // cp.async V(t+1) -> vb[(t+1)%3]
        if (mt < 63) {
            const char* src = (const char*)(g_Vbf + ((size_t)b * CC << 12))
                            + (mt + 1) * 64 * 2;
            char* dbuf = (char*)(sm + OFF_VB + ((mt + 1) % 3) * VB_SZ);
#pragma unroll
            for (int k = 0; k < 2; k++) {
                int q = tid + k * 256;
                int row = q >> 3, off = (q & 7) * 16;
                uint32_t dst = (uint32_t)__cvta_generic_to_shared(
                    dbuf + row * 144 + off);
                cp_async16(dst, src + ((size_t)row << 13) + off);
            }
            asm volatile("cp.async.commit_group;");
            asm volatile("cp.async.wait_group 1;");  // V(t) arrived
        } else {
            asm volatile("cp.async.wait_group 0;");
        }
        __syncthreads();    // THE barrier: A(t) visible, V(t) visible

        // phase B(t)
        const uint32_t* sVb = sm + OFF_VB + (mt % 3) * VB_SZ;
#pragma unroll
        for (int ks = 0; ks < 2; ks++) {
            const int colb = mh * 16 + ks * 8 + tg;
            uint32_t a[2][4];
#pragma unroll
            for (int mf = 0; mf < 2; mf++) {
                const uint32_t* ap = sPb + (Mwoff + mf * 16 + g) * 36 + colb;
                a[mf][0] = ap[0];
                a[mf][1] = ap[8 * 36];
                a[mf][2] = ap[4];
                a[mf][3] = ap[8 * 36 + 4];
            }
#pragma unroll
            for (int nf = 0; nf < 8; nf++) {
                const uint32_t* bp = sVb + (nf * 8 + g) * 36 + colb;
                uint32_t b0 = bp[0], b1 = bp[4];
                mma_bf16(acc + 0 * 32 + nf * 4, a[0], b0, b1);
                mma_bf16(acc + 1 * 32 + nf * 4, a[1], b0, b1);
            }
        }
    }

    // ---- epilogue: reduce m-halves across warp pairs, add O0, store ----
    __syncthreads();
    float* sred = (float*)sm;
    if (wid >= 4) {
        float* dst = sred + (wid - 4) * 2176 + lane * 68;
#pragma unroll
        for (int i = 0; i < 64; i++) dst[i] = acc[i];
    }
    __syncthreads();
    if (wid < 4) {
        const float* src = sred + wid * 2176 + lane * 68;
#pragma unroll
        for (int i = 0; i < 64; i++) acc[i] += src[i];
#pragma unroll
        for (int mf = 0; mf < 2; mf++)
#pragma unroll
            for (int nf = 0; nf < 8; nf++) {
                int n = n_base + Mwoff + mf * 16 + g;
                int c = nf * 8 + tg * 2;
                float o0a_ = __ldg(g_O0 + b * CC + c);
                float o0b_ = __ldg(g_O0 + b * CC + c + 1);
                float* o = out + (((size_t)b * CC + c) << 12) + n;
                const float* ac = acc + mf * 32 + nf * 4;
                o[0]        = ac[0] + o0a_;
                o[4096]     = ac[1] + o0b_;
                o[8]        = ac[2] + o0a_;
                o[4096 + 8] = ac[3] + o0b_;
            }
    }
}

// ---------------- launch ----------------
extern "C" void kernel_launch(void* const* d_in, const int* in_sizes, int n_in,
                              void* d_out, int out_size)
{
    const float* x  = (const float*)d_in[0];
    const float* Wq = (const float*)d_in[1];
    const float* bq = (const float*)d_in[2];
    const float* Wk = (const float*)d_in[3];
    const float* bk = (const float*)d_in[4];
    const float* Wv = (const float*)d_in[5];
    const float* bv = (const float*)d_in[6];
    float* out = (float*)d_out;

    cudaFuncSetAttribute(out_kernel, cudaFuncAttributeMaxDynamicSharedMemorySize, OUT_SMEM);

    proj_kernel<<<dim3(16, BATCH), 256>>>(x, Wq, bq, Wk, bk, Wv, bv);
    zr_kernel<<<dim3(64, 4, BATCH), 256>>>();
    rza_kernel<<<128, 256>>>();
    o0a_kernel<<<dim3(CC, BATCH), 256>>>(x);
    o0b_kernel<<<BATCH, 64>>>(Wv, bv);
    out_kernel<<<dim3(32, BATCH), 256, OUT_SMEM>>>(out);
}